// round 10
// baseline (speedup 1.0000x reference)
#include <cuda_runtime.h>
#include <cuda_fp16.h>
#include <cstdint>

#define NB 256   // batch
#define ND 16    // manifold dim
#define NH 128   // hidden
#define R2H 256  // 2H
#define IPB 4    // i's per block in k_main

// ---- scratch (device globals; no allocation) ----
__device__ float g_metric[NB * 256];          // metric[b][i*16+j]
__device__ float g_PB[NB * 256];              // points@rW1[0:16] + rb1
__device__ float g_Spart[NB * ND * 256];      // per-(b,i) partial hidden sums

__device__ __forceinline__ __half2 tanh2h(__half2 x) {
    uint32_t xi, yi;
    xi = *reinterpret_cast<uint32_t*>(&x);
    asm("tanh.approx.f16x2 %0, %1;" : "=r"(yi) : "r"(xi));
    __half2 y = *reinterpret_cast<__half2*>(&yi);
    return y;
}
__device__ __forceinline__ __half2 u2h2(uint32_t u) {
    return *reinterpret_cast<__half2*>(&u);
}

// ============================================================================
// K1 (slim): metric + PB only.  grid=NB, 256 threads (high co-residency).
// ============================================================================
__global__ __launch_bounds__(256) void k_metric(
    const float* __restrict__ points,
    const float* __restrict__ mW1, const float* __restrict__ mb1,
    const float* __restrict__ mW2, const float* __restrict__ mb2,
    const float* __restrict__ rW1, const float* __restrict__ rb1)
{
    int b = blockIdx.x;
    int t = threadIdx.x;

    __shared__ float pts[ND];
    __shared__ float mh[NH];
    __shared__ float mraw[256];

    if (t < ND) pts[t] = points[b * ND + t];
    __syncthreads();

    if (t < NH) {
        float a = mb1[t];
        #pragma unroll
        for (int p = 0; p < ND; p++) a = fmaf(pts[p], mW1[p * NH + t], a);
        mh[t] = fmaxf(a, 0.0f);
    }
    __syncthreads();

    // mraw[t] = mb2[t] + sum_h mh[h]*mW2[h][t] — 4 interleaved acc chains
    {
        float a0 = 0.f, a1 = 0.f, a2 = 0.f, a3 = 0.f;
        #pragma unroll 8
        for (int h = 0; h < 32; h++) {
            a0 = fmaf(mh[h],      mW2[h * 256 + t],          a0);
            a1 = fmaf(mh[32 + h], mW2[(32 + h) * 256 + t],   a1);
            a2 = fmaf(mh[64 + h], mW2[(64 + h) * 256 + t],   a2);
            a3 = fmaf(mh[96 + h], mW2[(96 + h) * 256 + t],   a3);
        }
        mraw[t] = mb2[t] + (a0 + a1) + (a2 + a3);
    }
    __syncthreads();

    {
        int i = t >> 4, j = t & 15;
        float m = 0.5f * (mraw[i * 16 + j] + mraw[j * 16 + i])
                + (i == j ? 1e-6f : 0.0f);
        g_metric[b * 256 + t] = m;
        // PB[b][o] = rb1[o] + sum_p points[p]*rW1[p][o]
        float a = rb1[t];
        #pragma unroll
        for (int p = 0; p < ND; p++) a = fmaf(pts[p], rW1[p * 256 + t], a);
        g_PB[b * 256 + t] = a;
    }
}

// ============================================================================
// K2: main fused kernel. One block per (i-quad, b); 256 threads.
//   Preamble: per-thread o computes pm[4] (PB+M1) and M2[16 j] -> smem slab.
//   Stage A: fp16x2 MLP for 4 i's at once.
//   Stage B: fp16 HFMA2 dot products; fp32 pm/m2/relu/sum.
// ============================================================================
struct WPack { __half2 w0, w1, w2, b; };   // 16 bytes

__global__ __launch_bounds__(256, 3) void k_main(
    const float* __restrict__ cW1, const float* __restrict__ cb1,
    const float* __restrict__ cW2, const float* __restrict__ cb2,
    const float* __restrict__ rW1)
{
    int i0 = blockIdx.x * IPB;  // 0,4,8,12
    int b  = blockIdx.y;        // 0..255
    int t  = threadIdx.x;       // 0..255

    __shared__ float met[256];
    __shared__ __align__(16) WPack   sW[NH / 2];
    __shared__ __align__(4)  __half2 sV[NH / 2];
    __shared__ __align__(16) __half  chs[IPB][256];
    __shared__ float m2s[ND][256];     // M2[j][o], own-column access

    met[t] = g_metric[b * 256 + t];
    if (t < NH / 2) {
        int q = t;
        WPack w;
        w.w0 = __floats2half2_rn(cW1[2 * q],          cW1[2 * q + 1]);
        w.w1 = __floats2half2_rn(cW1[NH + 2 * q],     cW1[NH + 2 * q + 1]);
        w.w2 = __floats2half2_rn(cW1[2 * NH + 2 * q], cW1[2 * NH + 2 * q + 1]);
        w.b  = __floats2half2_rn(cb1[2 * q],          cb1[2 * q + 1]);
        sW[q] = w;
        sV[q] = __floats2half2_rn(cW2[2 * q], cW2[2 * q + 1]);
    }
    __syncthreads();

    // ---- Preamble: pm[4] and M2[16] for o=t (no syncs needed: own column) ----
    float pm[IPB];
    {
        int o = t;
        float rwA[ND], rwB[ND];
        #pragma unroll
        for (int p = 0; p < ND; p++) {
            rwA[p] = rW1[(16 + p) * 256 + o];
            rwB[p] = rW1[(32 + p) * 256 + o];
        }
        float pb = g_PB[b * 256 + o];
        #pragma unroll
        for (int ii = 0; ii < IPB; ii++) {
            float a1 = 0.0f;
            #pragma unroll
            for (int p = 0; p < ND; p++)
                a1 = fmaf(met[(i0 + ii) * 16 + p], rwA[p], a1);
            pm[ii] = pb + a1;
        }
        #pragma unroll
        for (int j = 0; j < ND; j++) {
            float a2 = 0.0f;
            #pragma unroll
            for (int p = 0; p < ND; p++)
                a2 = fmaf(met[j * 16 + p], rwB[p], a2);
            m2s[j][o] = a2;
        }
    }

    // ---- Stage A: christoffel for (i0..i0+3, j=t>>4, k=t&15) ----
    {
        int j = t >> 4, k = t & 15;
        __half2 mjk2 = __float2half2_rn(met[j * 16 + k]);
        __half2 mij2[IPB], mki2[IPB];
        #pragma unroll
        for (int ii = 0; ii < IPB; ii++) {
            mij2[ii] = __float2half2_rn(met[(i0 + ii) * 16 + j]);
            mki2[ii] = __float2half2_rn(met[(i0 + ii) * 16 + k]);  // symmetric
        }
        const __half2 z2 = __float2half2_rn(0.0f);

        float facc[IPB];
        #pragma unroll
        for (int ii = 0; ii < IPB; ii++) facc[ii] = cb2[0];

        #pragma unroll
        for (int blk = 0; blk < 8; blk++) {
            __half2 acc[IPB];
            #pragma unroll
            for (int ii = 0; ii < IPB; ii++) acc[ii] = z2;
            #pragma unroll
            for (int r = 0; r < 8; r++) {
                int q = blk * 8 + r;
                WPack w = sW[q];
                __half2 v = sV[q];
                #pragma unroll
                for (int ii = 0; ii < IPB; ii++) {
                    __half2 x = __hfma2(mij2[ii], w.w0, w.b);
                    x = __hfma2(mjk2, w.w1, x);
                    x = __hfma2(mki2[ii], w.w2, x);
                    acc[ii] = __hfma2(v, tanh2h(x), acc[ii]);
                }
            }
            #pragma unroll
            for (int ii = 0; ii < IPB; ii++) {
                float2 f = __half22float2(acc[ii]);
                facc[ii] += f.x + f.y;
            }
        }
        #pragma unroll
        for (int ii = 0; ii < IPB; ii++)
            chs[ii][t] = __float2half(facc[ii]);
    }
    __syncthreads();

    // ---- Stage B: hidden layer of ricci net, reduced over j, 4 i's ----
    {
        int o = t;
        const float* rW1c = rW1 + 48 * 256;
        __half2 rwh[8];
        #pragma unroll
        for (int q = 0; q < 8; q++)
            rwh[q] = __floats2half2_rn(rW1c[(2 * q) * 256 + o],
                                       rW1c[(2 * q + 1) * 256 + o]);

        float s[IPB];
        #pragma unroll
        for (int ii = 0; ii < IPB; ii++) s[ii] = 0.0f;
        const __half2 z2 = __float2half2_rn(0.0f);

        #pragma unroll 4
        for (int j = 0; j < ND; j++) {
            float m2 = m2s[j][o];
            #pragma unroll
            for (int ii = 0; ii < IPB; ii++) {
                const uint4* cp = (const uint4*)&chs[ii][j * 16];
                uint4 u0 = cp[0];
                uint4 u1 = cp[1];
                __half2 acc = z2;
                acc = __hfma2(u2h2(u0.x), rwh[0], acc);
                acc = __hfma2(u2h2(u0.y), rwh[1], acc);
                acc = __hfma2(u2h2(u0.z), rwh[2], acc);
                acc = __hfma2(u2h2(u0.w), rwh[3], acc);
                acc = __hfma2(u2h2(u1.x), rwh[4], acc);
                acc = __hfma2(u2h2(u1.y), rwh[5], acc);
                acc = __hfma2(u2h2(u1.z), rwh[6], acc);
                acc = __hfma2(u2h2(u1.w), rwh[7], acc);
                float2 f = __half22float2(acc);
                float a = pm[ii] + m2 + f.x + f.y;
                s[ii] += fmaxf(a, 0.0f);
            }
        }
        #pragma unroll
        for (int ii = 0; ii < IPB; ii++)
            g_Spart[(b * ND + i0 + ii) * 256 + o] = s[ii];
    }
}

// ============================================================================
// K3: reduce partials + output GEMM + symmetrize. grid=NB, 256 threads.
// ============================================================================
__global__ __launch_bounds__(256) void k_final(
    const float* __restrict__ rW2, const float* __restrict__ rb2,
    float* __restrict__ out)
{
    int b = blockIdx.x;
    int t = threadIdx.x;
    __shared__ float Ss[256];
    __shared__ float raw[256];

    float s = 0.0f;
    #pragma unroll
    for (int i = 0; i < ND; i++) s += g_Spart[(b * ND + i) * 256 + t];
    Ss[t] = s * (1.0f / 256.0f);
    __syncthreads();

    {
        float a0 = 0.f, a1 = 0.f, a2 = 0.f, a3 = 0.f;
        #pragma unroll 8
        for (int h = 0; h < 64; h++) {
            a0 = fmaf(Ss[h],       rW2[h * 256 + t],         a0);
            a1 = fmaf(Ss[64 + h],  rW2[(64 + h) * 256 + t],  a1);
            a2 = fmaf(Ss[128 + h], rW2[(128 + h) * 256 + t], a2);
            a3 = fmaf(Ss[192 + h], rW2[(192 + h) * 256 + t], a3);
        }
        raw[t] = rb2[t] + (a0 + a1) + (a2 + a3);
    }
    __syncthreads();

    int i = t >> 4, j = t & 15;
    out[b * 256 + t] = 0.5f * (raw[i * 16 + j] + raw[j * 16 + i]);
}

// ============================================================================
extern "C" void kernel_launch(void* const* d_in, const int* in_sizes, int n_in,
                              void* d_out, int out_size)
{
    const float* points = (const float*)d_in[0];
    const float* mW1    = (const float*)d_in[1];
    const float* mb1    = (const float*)d_in[2];
    const float* mW2    = (const float*)d_in[3];
    const float* mb2    = (const float*)d_in[4];
    const float* cW1    = (const float*)d_in[5];
    const float* cb1    = (const float*)d_in[6];
    const float* cW2    = (const float*)d_in[7];
    const float* cb2    = (const float*)d_in[8];
    const float* rW1    = (const float*)d_in[9];
    const float* rb1    = (const float*)d_in[10];
    const float* rW2    = (const float*)d_in[11];
    const float* rb2    = (const float*)d_in[12];
    float* out = (float*)d_out;

    k_metric<<<NB, 256>>>(points, mW1, mb1, mW2, mb2, rW1, rb1);
    dim3 grid2(ND / IPB, NB);
    k_main<<<grid2, 256>>>(cW1, cb1, cW2, cb2, rW1);
    k_final<<<NB, 256>>>(rW2, rb2, out);
}

// round 11
// speedup vs baseline: 1.0026x; 1.0026x over previous
#include <cuda_runtime.h>
#include <cuda_fp16.h>
#include <cstdint>

#define NB 256   // batch
#define ND 16    // manifold dim
#define NH 128   // hidden
#define R2H 256  // 2H
#define IPB 4    // i's per block in k_main

// ---- scratch (device globals; no allocation) ----
__device__ float g_Spart[NB * ND * 256];      // per-(b,i) partial hidden sums

__device__ __forceinline__ __half2 tanh2h(__half2 x) {
    uint32_t xi, yi;
    xi = *reinterpret_cast<uint32_t*>(&x);
    asm("tanh.approx.f16x2 %0, %1;" : "=r"(yi) : "r"(xi));
    __half2 y = *reinterpret_cast<__half2*>(&yi);
    return y;
}
__device__ __forceinline__ __half2 u2h2(uint32_t u) {
    return *reinterpret_cast<__half2*>(&u);
}

struct WPack { __half2 w0, w1, w2, b; };   // 16 bytes

// ============================================================================
// K_MAIN (fully fused): grid (ND/IPB, NB), 256 threads.
//   Phase 0: pts + christoffel weight conversion to smem
//   Phase 1: metric hidden layer (redundant x4 per b — hidden under MUFU work)
//   Phase 2: metric GEMM (4 interleaved acc chains, own column)
//   Phase 3: symmetrize + eps -> met
//   Preamble: pm[4] = PB + M1, m2s[16][o] (own-column, no sync needed)
//   Stage A: fp16x2 christoffel MLP for 4 i's
//   Stage B: fp16 HFMA2 ricci hidden sums
// ============================================================================
__global__ __launch_bounds__(256) void k_main(
    const float* __restrict__ points,
    const float* __restrict__ mW1, const float* __restrict__ mb1,
    const float* __restrict__ mW2, const float* __restrict__ mb2,
    const float* __restrict__ cW1, const float* __restrict__ cb1,
    const float* __restrict__ cW2, const float* __restrict__ cb2,
    const float* __restrict__ rW1, const float* __restrict__ rb1)
{
    int i0 = blockIdx.x * IPB;  // 0,4,8,12
    int b  = blockIdx.y;        // 0..255
    int t  = threadIdx.x;       // 0..255

    __shared__ float pts[ND];
    __shared__ float mh[NH];
    __shared__ float mraw[256];
    __shared__ float met[256];
    __shared__ __align__(16) WPack   sW[NH / 2];
    __shared__ __align__(4)  __half2 sV[NH / 2];
    __shared__ __align__(16) __half  chs[IPB][256];
    __shared__ float m2s[ND][256];     // M2[j][o], own-column access

    // ---- Phase 0: pts + weight conversion ----
    if (t < ND) pts[t] = points[b * ND + t];
    if (t < NH / 2) {
        int q = t;
        WPack w;
        w.w0 = __floats2half2_rn(cW1[2 * q],          cW1[2 * q + 1]);
        w.w1 = __floats2half2_rn(cW1[NH + 2 * q],     cW1[NH + 2 * q + 1]);
        w.w2 = __floats2half2_rn(cW1[2 * NH + 2 * q], cW1[2 * NH + 2 * q + 1]);
        w.b  = __floats2half2_rn(cb1[2 * q],          cb1[2 * q + 1]);
        sW[q] = w;
        sV[q] = __floats2half2_rn(cW2[2 * q], cW2[2 * q + 1]);
    }
    __syncthreads();

    // ---- Phase 1: metric hidden layer ----
    if (t < NH) {
        float a = mb1[t];
        #pragma unroll
        for (int p = 0; p < ND; p++) a = fmaf(pts[p], mW1[p * NH + t], a);
        mh[t] = fmaxf(a, 0.0f);
    }
    __syncthreads();

    // ---- Phase 2: metric GEMM (4 interleaved chains over h) ----
    {
        float a0 = 0.f, a1 = 0.f, a2 = 0.f, a3 = 0.f;
        #pragma unroll 8
        for (int h = 0; h < 32; h++) {
            a0 = fmaf(mh[h],      mW2[h * 256 + t],        a0);
            a1 = fmaf(mh[32 + h], mW2[(32 + h) * 256 + t], a1);
            a2 = fmaf(mh[64 + h], mW2[(64 + h) * 256 + t], a2);
            a3 = fmaf(mh[96 + h], mW2[(96 + h) * 256 + t], a3);
        }
        mraw[t] = mb2[t] + (a0 + a1) + (a2 + a3);
    }
    __syncthreads();

    // ---- Phase 3: symmetrize + eps ----
    {
        int i = t >> 4, j = t & 15;
        met[t] = 0.5f * (mraw[i * 16 + j] + mraw[j * 16 + i])
               + (i == j ? 1e-6f : 0.0f);
    }
    __syncthreads();

    // ---- Preamble: pm[4] (PB + M1) and M2[16] for o=t (own column) ----
    float pm[IPB];
    {
        int o = t;
        float rwA[ND], rwB[ND];
        #pragma unroll
        for (int p = 0; p < ND; p++) {
            rwA[p] = rW1[(16 + p) * 256 + o];
            rwB[p] = rW1[(32 + p) * 256 + o];
        }
        float pb = rb1[o];
        #pragma unroll
        for (int p = 0; p < ND; p++) pb = fmaf(pts[p], rW1[p * 256 + o], pb);
        #pragma unroll
        for (int ii = 0; ii < IPB; ii++) {
            float a1 = 0.0f;
            #pragma unroll
            for (int p = 0; p < ND; p++)
                a1 = fmaf(met[(i0 + ii) * 16 + p], rwA[p], a1);
            pm[ii] = pb + a1;
        }
        #pragma unroll
        for (int j = 0; j < ND; j++) {
            float a2 = 0.0f;
            #pragma unroll
            for (int p = 0; p < ND; p++)
                a2 = fmaf(met[j * 16 + p], rwB[p], a2);
            m2s[j][o] = a2;
        }
    }

    // ---- Stage A: christoffel for (i0..i0+3, j=t>>4, k=t&15) ----
    {
        int j = t >> 4, k = t & 15;
        __half2 mjk2 = __float2half2_rn(met[j * 16 + k]);
        __half2 mij2[IPB], mki2[IPB];
        #pragma unroll
        for (int ii = 0; ii < IPB; ii++) {
            mij2[ii] = __float2half2_rn(met[(i0 + ii) * 16 + j]);
            mki2[ii] = __float2half2_rn(met[(i0 + ii) * 16 + k]);  // symmetric
        }
        const __half2 z2 = __float2half2_rn(0.0f);

        float facc[IPB];
        #pragma unroll
        for (int ii = 0; ii < IPB; ii++) facc[ii] = cb2[0];

        #pragma unroll
        for (int blk = 0; blk < 8; blk++) {
            __half2 acc[IPB];
            #pragma unroll
            for (int ii = 0; ii < IPB; ii++) acc[ii] = z2;
            #pragma unroll
            for (int r = 0; r < 8; r++) {
                int q = blk * 8 + r;
                WPack w = sW[q];
                __half2 v = sV[q];
                #pragma unroll
                for (int ii = 0; ii < IPB; ii++) {
                    __half2 x = __hfma2(mij2[ii], w.w0, w.b);
                    x = __hfma2(mjk2, w.w1, x);
                    x = __hfma2(mki2[ii], w.w2, x);
                    acc[ii] = __hfma2(v, tanh2h(x), acc[ii]);
                }
            }
            #pragma unroll
            for (int ii = 0; ii < IPB; ii++) {
                float2 f = __half22float2(acc[ii]);
                facc[ii] += f.x + f.y;
            }
        }
        #pragma unroll
        for (int ii = 0; ii < IPB; ii++)
            chs[ii][t] = __float2half(facc[ii]);
    }
    __syncthreads();

    // ---- Stage B: hidden layer of ricci net, reduced over j, 4 i's ----
    {
        int o = t;
        const float* rW1c = rW1 + 48 * 256;
        __half2 rwh[8];
        #pragma unroll
        for (int q = 0; q < 8; q++)
            rwh[q] = __floats2half2_rn(rW1c[(2 * q) * 256 + o],
                                       rW1c[(2 * q + 1) * 256 + o]);

        float s[IPB];
        #pragma unroll
        for (int ii = 0; ii < IPB; ii++) s[ii] = 0.0f;
        const __half2 z2 = __float2half2_rn(0.0f);

        #pragma unroll 4
        for (int j = 0; j < ND; j++) {
            float m2 = m2s[j][o];
            #pragma unroll
            for (int ii = 0; ii < IPB; ii++) {
                const uint4* cp = (const uint4*)&chs[ii][j * 16];
                uint4 u0 = cp[0];
                uint4 u1 = cp[1];
                __half2 acc = z2;
                acc = __hfma2(u2h2(u0.x), rwh[0], acc);
                acc = __hfma2(u2h2(u0.y), rwh[1], acc);
                acc = __hfma2(u2h2(u0.z), rwh[2], acc);
                acc = __hfma2(u2h2(u0.w), rwh[3], acc);
                acc = __hfma2(u2h2(u1.x), rwh[4], acc);
                acc = __hfma2(u2h2(u1.y), rwh[5], acc);
                acc = __hfma2(u2h2(u1.z), rwh[6], acc);
                acc = __hfma2(u2h2(u1.w), rwh[7], acc);
                float2 f = __half22float2(acc);
                float a = pm[ii] + m2 + f.x + f.y;
                s[ii] += fmaxf(a, 0.0f);
            }
        }
        #pragma unroll
        for (int ii = 0; ii < IPB; ii++)
            g_Spart[(b * ND + i0 + ii) * 256 + o] = s[ii];
    }
}

// ============================================================================
// K3: reduce partials + output GEMM + symmetrize. grid=NB, 256 threads.
// ============================================================================
__global__ __launch_bounds__(256) void k_final(
    const float* __restrict__ rW2, const float* __restrict__ rb2,
    float* __restrict__ out)
{
    int b = blockIdx.x;
    int t = threadIdx.x;
    __shared__ float Ss[256];
    __shared__ float raw[256];

    float s = 0.0f;
    #pragma unroll
    for (int i = 0; i < ND; i++) s += g_Spart[(b * ND + i) * 256 + t];
    Ss[t] = s * (1.0f / 256.0f);
    __syncthreads();

    {
        float a0 = 0.f, a1 = 0.f, a2 = 0.f, a3 = 0.f;
        #pragma unroll 8
        for (int h = 0; h < 64; h++) {
            a0 = fmaf(Ss[h],       rW2[h * 256 + t],         a0);
            a1 = fmaf(Ss[64 + h],  rW2[(64 + h) * 256 + t],  a1);
            a2 = fmaf(Ss[128 + h], rW2[(128 + h) * 256 + t], a2);
            a3 = fmaf(Ss[192 + h], rW2[(192 + h) * 256 + t], a3);
        }
        raw[t] = rb2[t] + (a0 + a1) + (a2 + a3);
    }
    __syncthreads();

    int i = t >> 4, j = t & 15;
    out[b * 256 + t] = 0.5f * (raw[i * 16 + j] + raw[j * 16 + i]);
}

// ============================================================================
extern "C" void kernel_launch(void* const* d_in, const int* in_sizes, int n_in,
                              void* d_out, int out_size)
{
    const float* points = (const float*)d_in[0];
    const float* mW1    = (const float*)d_in[1];
    const float* mb1    = (const float*)d_in[2];
    const float* mW2    = (const float*)d_in[3];
    const float* mb2    = (const float*)d_in[4];
    const float* cW1    = (const float*)d_in[5];
    const float* cb1    = (const float*)d_in[6];
    const float* cW2    = (const float*)d_in[7];
    const float* cb2    = (const float*)d_in[8];
    const float* rW1    = (const float*)d_in[9];
    const float* rb1    = (const float*)d_in[10];
    const float* rW2    = (const float*)d_in[11];
    const float* rb2    = (const float*)d_in[12];
    float* out = (float*)d_out;

    dim3 grid2(ND / IPB, NB);
    k_main<<<grid2, 256>>>(points, mW1, mb1, mW2, mb2,
                           cW1, cb1, cW2, cb2, rW1, rb1);
    k_final<<<NB, 256>>>(rW2, rb2, out);
}

// round 12
// speedup vs baseline: 1.0296x; 1.0270x over previous
#include <cuda_runtime.h>
#include <cuda_fp16.h>
#include <cstdint>

#define NB 256   // batch
#define ND 16    // manifold dim
#define NH 128   // hidden
#define R2H 256  // 2H
#define IPB 4    // i's per block in k_main

// ---- scratch (device globals; no allocation) ----
__device__ float g_metric[NB * 256];          // metric[b][i*16+j]
__device__ float g_PB[NB * 256];              // points@rW1[0:16] + rb1
__device__ float g_M1[NB * ND * 256];         // M1[b][i][o]
__device__ float g_M2[NB * ND * 256];         // M2[b][j][o]
__device__ float g_Spart[NB * ND * 256];      // per-(b,i) partial hidden sums
__device__ float g_raw[NB * 256];             // pre-symmetrization ricci output

__device__ __forceinline__ __half2 tanh2h(__half2 x) {
    uint32_t xi, yi;
    xi = *reinterpret_cast<uint32_t*>(&x);
    asm("tanh.approx.f16x2 %0, %1;" : "=r"(yi) : "r"(xi));
    __half2 y = *reinterpret_cast<__half2*>(&yi);
    return y;
}
__device__ __forceinline__ __half2 u2h2(uint32_t u) {
    return *reinterpret_cast<__half2*>(&u);
}

// ============================================================================
// K1: metric + PB + M1/M2.  grid=NB, 1024 threads.  (R9 verbatim)
// ============================================================================
__global__ __launch_bounds__(1024) void k_metric(
    const float* __restrict__ points,
    const float* __restrict__ mW1, const float* __restrict__ mb1,
    const float* __restrict__ mW2, const float* __restrict__ mb2,
    const float* __restrict__ rW1, const float* __restrict__ rb1)
{
    int b = blockIdx.x;
    int t = threadIdx.x;
    int g2 = t >> 8, o = t & 255;

    __shared__ float pts[ND];
    __shared__ float mh[NH];
    __shared__ __align__(16) float part[16][256];
    __shared__ float met[256];

    float rwA[ND], rwB[ND];
    #pragma unroll
    for (int p = 0; p < ND; p++) {
        rwA[p] = rW1[(16 + p) * 256 + o];
        rwB[p] = rW1[(32 + p) * 256 + o];
    }

    if (t < ND) pts[t] = points[b * ND + t];
    __syncthreads();

    if (t < NH) {
        float a = mb1[t];
        #pragma unroll
        for (int p = 0; p < ND; p++) a = fmaf(pts[p], mW1[p * NH + t], a);
        mh[t] = fmaxf(a, 0.0f);
    }
    __syncthreads();

    {
        int g = t >> 6, q = t & 63;
        float4 acc = make_float4(0.f, 0.f, 0.f, 0.f);
        #pragma unroll
        for (int h = 0; h < 8; h++) {
            int hh = g * 8 + h;
            float4 w = *(const float4*)&mW2[hh * 256 + 4 * q];
            float m = mh[hh];
            acc.x = fmaf(m, w.x, acc.x);
            acc.y = fmaf(m, w.y, acc.y);
            acc.z = fmaf(m, w.z, acc.z);
            acc.w = fmaf(m, w.w, acc.w);
        }
        *(float4*)&part[g][4 * q] = acc;
    }
    __syncthreads();

    if (t < 256) {
        float a = mb2[t];
        #pragma unroll
        for (int g = 0; g < 16; g++) a += part[g][t];
        part[0][t] = a;
    }
    __syncthreads();

    if (t < 256) {
        int i = t >> 4, j = t & 15;
        float m = 0.5f * (part[0][i * 16 + j] + part[0][j * 16 + i])
                + (i == j ? 1e-6f : 0.0f);
        met[t] = m;
        g_metric[b * 256 + t] = m;
        float a = rb1[t];
        #pragma unroll
        for (int p = 0; p < ND; p++) a = fmaf(pts[p], rW1[p * 256 + t], a);
        g_PB[b * 256 + t] = a;
    }
    __syncthreads();

    #pragma unroll
    for (int ii = 0; ii < 4; ii++) {
        int i0 = g2 * 4 + ii;
        float a1 = 0.0f, a2 = 0.0f;
        #pragma unroll
        for (int p = 0; p < ND; p++) {
            float mv = met[i0 * 16 + p];
            a1 = fmaf(mv, rwA[p], a1);
            a2 = fmaf(mv, rwB[p], a2);
        }
        g_M1[(b * ND + i0) * 256 + o] = a1;
        g_M2[(b * ND + i0) * 256 + o] = a2;
    }
}

// ============================================================================
// K2: main fused kernel.  (R9 verbatim: IPB=4, fp16 Stage A + B)
// ============================================================================
struct WPack { __half2 w0, w1, w2, b; };   // 16 bytes

__global__ __launch_bounds__(256) void k_main(
    const float* __restrict__ cW1, const float* __restrict__ cb1,
    const float* __restrict__ cW2, const float* __restrict__ cb2,
    const float* __restrict__ rW1)
{
    int i0 = blockIdx.x * IPB;  // 0,4,8,12
    int b  = blockIdx.y;        // 0..255
    int t  = threadIdx.x;       // 0..255

    __shared__ float met[256];
    __shared__ __align__(16) WPack   sW[NH / 2];
    __shared__ __align__(4)  __half2 sV[NH / 2];
    __shared__ __align__(16) __half  chs[IPB][256];

    met[t] = g_metric[b * 256 + t];
    if (t < NH / 2) {
        int q = t;
        WPack w;
        w.w0 = __floats2half2_rn(cW1[2 * q],          cW1[2 * q + 1]);
        w.w1 = __floats2half2_rn(cW1[NH + 2 * q],     cW1[NH + 2 * q + 1]);
        w.w2 = __floats2half2_rn(cW1[2 * NH + 2 * q], cW1[2 * NH + 2 * q + 1]);
        w.b  = __floats2half2_rn(cb1[2 * q],          cb1[2 * q + 1]);
        sW[q] = w;
        sV[q] = __floats2half2_rn(cW2[2 * q], cW2[2 * q + 1]);
    }
    __syncthreads();

    // ---- Stage A: christoffel for (i0..i0+3, j=t>>4, k=t&15) ----
    {
        int j = t >> 4, k = t & 15;
        __half2 mjk2 = __float2half2_rn(met[j * 16 + k]);
        __half2 mij2[IPB], mki2[IPB];
        #pragma unroll
        for (int ii = 0; ii < IPB; ii++) {
            mij2[ii] = __float2half2_rn(met[(i0 + ii) * 16 + j]);
            mki2[ii] = __float2half2_rn(met[(i0 + ii) * 16 + k]);  // symmetric
        }
        const __half2 z2 = __float2half2_rn(0.0f);

        float facc[IPB];
        #pragma unroll
        for (int ii = 0; ii < IPB; ii++) facc[ii] = cb2[0];

        #pragma unroll
        for (int blk = 0; blk < 8; blk++) {
            __half2 acc[IPB];
            #pragma unroll
            for (int ii = 0; ii < IPB; ii++) acc[ii] = z2;
            #pragma unroll
            for (int r = 0; r < 8; r++) {
                int q = blk * 8 + r;
                WPack w = sW[q];
                __half2 v = sV[q];
                #pragma unroll
                for (int ii = 0; ii < IPB; ii++) {
                    __half2 x = __hfma2(mij2[ii], w.w0, w.b);
                    x = __hfma2(mjk2, w.w1, x);
                    x = __hfma2(mki2[ii], w.w2, x);
                    acc[ii] = __hfma2(v, tanh2h(x), acc[ii]);
                }
            }
            #pragma unroll
            for (int ii = 0; ii < IPB; ii++) {
                float2 f = __half22float2(acc[ii]);
                facc[ii] += f.x + f.y;
            }
        }
        #pragma unroll
        for (int ii = 0; ii < IPB; ii++)
            chs[ii][t] = __float2half(facc[ii]);
    }
    __syncthreads();

    // ---- Stage B: hidden layer of ricci net, reduced over j, 4 i's ----
    {
        int o = t;
        const float* rW1c = rW1 + 48 * 256;
        __half2 rwh[8];
        #pragma unroll
        for (int q = 0; q < 8; q++)
            rwh[q] = __floats2half2_rn(rW1c[(2 * q) * 256 + o],
                                       rW1c[(2 * q + 1) * 256 + o]);

        float pm[IPB], s[IPB];
        float pb = g_PB[b * 256 + o];
        #pragma unroll
        for (int ii = 0; ii < IPB; ii++) {
            pm[ii] = pb + g_M1[(b * ND + i0 + ii) * 256 + o];
            s[ii] = 0.0f;
        }
        const __half2 z2 = __float2half2_rn(0.0f);

        #pragma unroll 4
        for (int j = 0; j < ND; j++) {
            float m2 = g_M2[(b * ND + j) * 256 + o];
            #pragma unroll
            for (int ii = 0; ii < IPB; ii++) {
                const uint4* cp = (const uint4*)&chs[ii][j * 16];
                uint4 u0 = cp[0];
                uint4 u1 = cp[1];
                __half2 acc = z2;
                acc = __hfma2(u2h2(u0.x), rwh[0], acc);
                acc = __hfma2(u2h2(u0.y), rwh[1], acc);
                acc = __hfma2(u2h2(u0.z), rwh[2], acc);
                acc = __hfma2(u2h2(u0.w), rwh[3], acc);
                acc = __hfma2(u2h2(u1.x), rwh[4], acc);
                acc = __hfma2(u2h2(u1.y), rwh[5], acc);
                acc = __hfma2(u2h2(u1.z), rwh[6], acc);
                acc = __hfma2(u2h2(u1.w), rwh[7], acc);
                float2 f = __half22float2(acc);
                float a = pm[ii] + m2 + f.x + f.y;
                s[ii] += fmaxf(a, 0.0f);
            }
        }
        #pragma unroll
        for (int ii = 0; ii < IPB; ii++)
            g_Spart[(b * ND + i0 + ii) * 256 + o] = s[ii];
    }
}

// ============================================================================
// K3a: reduce partials + output GEMM (64-output slice per block).
//      grid (NB, 4), 256 threads. 4 threads per output, h split 4x64.
// ============================================================================
__global__ __launch_bounds__(256) void k_gemm(
    const float* __restrict__ rW2, const float* __restrict__ rb2)
{
    int b = blockIdx.x;
    int y = blockIdx.y;          // output slice: o in [64y, 64y+64)
    int t = threadIdx.x;

    __shared__ float Ss[256];
    __shared__ float partial[4][64];

    // full Ss (redundant x4 across y-blocks; only 16 loads per thread)
    {
        float s = 0.0f;
        #pragma unroll
        for (int i = 0; i < ND; i++) s += g_Spart[(b * ND + i) * 256 + t];
        Ss[t] = s * (1.0f / 256.0f);
    }
    __syncthreads();

    // thread (hg = t>>6, u = t&63) accumulates h in [64*hg, 64*hg+64) for o=64y+u
    {
        int u = t & 63, hg = t >> 6;
        int o = 64 * y + u;
        int h0 = 64 * hg;
        float a = 0.0f;
        #pragma unroll 8
        for (int h = 0; h < 64; h++)
            a = fmaf(Ss[h0 + h], rW2[(h0 + h) * 256 + o], a);
        partial[hg][u] = a;
    }
    __syncthreads();

    if (t < 64) {
        int o = 64 * y + t;
        g_raw[b * 256 + o] = rb2[o] + (partial[0][t] + partial[1][t])
                                    + (partial[2][t] + partial[3][t]);
    }
}

// ============================================================================
// K3b: symmetrize.  grid NB, 256 threads. 2 loads + 1 store.
// ============================================================================
__global__ __launch_bounds__(256) void k_sym(float* __restrict__ out)
{
    int b = blockIdx.x;
    int t = threadIdx.x;
    int i = t >> 4, j = t & 15;
    out[b * 256 + t] = 0.5f * (g_raw[b * 256 + i * 16 + j]
                             + g_raw[b * 256 + j * 16 + i]);
}

// ============================================================================
extern "C" void kernel_launch(void* const* d_in, const int* in_sizes, int n_in,
                              void* d_out, int out_size)
{
    const float* points = (const float*)d_in[0];
    const float* mW1    = (const float*)d_in[1];
    const float* mb1    = (const float*)d_in[2];
    const float* mW2    = (const float*)d_in[3];
    const float* mb2    = (const float*)d_in[4];
    const float* cW1    = (const float*)d_in[5];
    const float* cb1    = (const float*)d_in[6];
    const float* cW2    = (const float*)d_in[7];
    const float* cb2    = (const float*)d_in[8];
    const float* rW1    = (const float*)d_in[9];
    const float* rb1    = (const float*)d_in[10];
    const float* rW2    = (const float*)d_in[11];
    const float* rb2    = (const float*)d_in[12];
    float* out = (float*)d_out;

    k_metric<<<NB, 1024>>>(points, mW1, mb1, mW2, mb2, rW1, rb1);
    dim3 grid2(ND / IPB, NB);
    k_main<<<grid2, 256>>>(cW1, cb1, cW2, cb2, rW1);
    dim3 grid3(NB, 4);
    k_gemm<<<grid3, 256>>>(rW2, rb2);
    k_sym<<<NB, 256>>>(out);
}